// round 11
// baseline (speedup 1.0000x reference)
#include <cuda_runtime.h>
#include <cuda_bf16.h>
#include <math.h>

#define N_NODES 50000
#define N_EDGES 800000
#define DIM_IN  128
#define DIM_H   64
#define DIM_OUT 16

// Scratch (allocation-free: __device__ globals)
__device__ __align__(16) float g_A[N_NODES * DIM_H];    // gemm1 out
__device__ __align__(16) float g_B[N_NODES * DIM_H];    // spmm64 out
__device__ __align__(16) float g_C[N_NODES * DIM_OUT];  // tanh(B)@W23
__device__ __align__(16) float g_U[N_NODES * DIM_OUT];  // spmm16 #1 out
__device__ __align__(16) float g_D[N_NODES * DIM_OUT];  // spmm16 #2 out
__device__ __align__(16) float g_W23[DIM_H * DIM_OUT];  // W2@W3

// CSR build scratch
__device__ int  g_cnt[N_NODES];          // per-node in-degree histogram
__device__ int  g_cur[N_NODES];          // scatter cursors
__device__ int  g_rowptr[N_NODES + 1];   // CSR row pointers (by dst)
__device__ int  g_bsum[256];             // scan block sums
__device__ __align__(8) int2 g_spack[N_EDGES];  // dst-sorted (src, val_bits)

// ---------------------------------------------------------------------------
// CSR build step 1: zero histogram
// ---------------------------------------------------------------------------
__global__ void zero_cnt_kernel(int* __restrict__ cnt, int n) {
    int i = blockIdx.x * blockDim.x + threadIdx.x;
    if (i < n) cnt[i] = 0;
}

// ---------------------------------------------------------------------------
// CSR build step 2: histogram of dst
// ---------------------------------------------------------------------------
__global__ void hist_kernel(const int* __restrict__ dst, int* __restrict__ cnt, int E) {
    int e = blockIdx.x * blockDim.x + threadIdx.x;
    if (e < E) atomicAdd(&cnt[dst[e]], 1);
}

// ---------------------------------------------------------------------------
// CSR build step 3a: per-block exclusive scan (512/block), block totals out
// ---------------------------------------------------------------------------
__global__ void scan1_kernel(const int* __restrict__ cnt, int* __restrict__ rowptr,
                             int* __restrict__ bsum, int n) {
    __shared__ int sh[512];
    int tid = threadIdx.x;
    int i = blockIdx.x * 512 + tid;
    int v = (i < n) ? cnt[i] : 0;
    sh[tid] = v;
    __syncthreads();
    #pragma unroll
    for (int off = 1; off < 512; off <<= 1) {
        int t = (tid >= off) ? sh[tid - off] : 0;
        __syncthreads();
        sh[tid] += t;
        __syncthreads();
    }
    if (i < n) rowptr[i] = sh[tid] - v;   // exclusive
    if (tid == 511) bsum[blockIdx.x] = sh[511];
}

// ---------------------------------------------------------------------------
// CSR build step 3b: scan block totals (single block, nb <= 128)
// ---------------------------------------------------------------------------
__global__ void scan2_kernel(int* __restrict__ bsum, int nb) {
    __shared__ int sh[128];
    int tid = threadIdx.x;
    int v = (tid < nb) ? bsum[tid] : 0;
    sh[tid] = v;
    __syncthreads();
    #pragma unroll
    for (int off = 1; off < 128; off <<= 1) {
        int t = (tid >= off) ? sh[tid - off] : 0;
        __syncthreads();
        sh[tid] += t;
        __syncthreads();
    }
    if (tid < nb) bsum[tid] = sh[tid] - v;   // exclusive
}

// ---------------------------------------------------------------------------
// CSR build step 3c: add block offsets, init cursors, set rowptr[n]=E
// ---------------------------------------------------------------------------
__global__ void scan3_kernel(int* __restrict__ rowptr, const int* __restrict__ bsum,
                             int* __restrict__ cur, int n, int E) {
    int i = blockIdx.x * blockDim.x + threadIdx.x;
    if (i < n) {
        int v = rowptr[i] + bsum[i >> 9];
        rowptr[i] = v;
        cur[i] = v;
    }
    if (i == 0) rowptr[n] = E;
}

// ---------------------------------------------------------------------------
// CSR build step 4: scatter edges into dst-sorted pack
// ---------------------------------------------------------------------------
__global__ void scatter_kernel(const int* __restrict__ src, const int* __restrict__ dst,
                               const float* __restrict__ val, int* __restrict__ cur,
                               int2* __restrict__ spack, int E) {
    int e = blockIdx.x * blockDim.x + threadIdx.x;
    if (e >= E) return;
    int d = dst[e];
    int p = atomicAdd(&cur[d], 1);
    spack[p] = make_int2(src[e], __float_as_int(val[e]));
}

// ---------------------------------------------------------------------------
// W23 = W2[64,64] @ W3[64,16]   (tiny, one-off)
// ---------------------------------------------------------------------------
__global__ void w23_kernel(const float* __restrict__ W2,
                           const float* __restrict__ W3,
                           float* __restrict__ W23) {
    int i = blockIdx.x * blockDim.x + threadIdx.x;
    if (i >= DIM_H * DIM_OUT) return;
    int r = i / DIM_OUT, c = i % DIM_OUT;
    float s = 0.f;
    #pragma unroll 8
    for (int k = 0; k < DIM_H; k++)
        s = fmaf(W2[r * DIM_H + k], W3[k * DIM_OUT + c], s);
    W23[i] = s;
}

// ---------------------------------------------------------------------------
// Register-tiled GEMM: out[n, DOUT] = in[n, DIN] @ W[DIN, DOUT]
// ---------------------------------------------------------------------------
template <int DIN, int DOUT>
__global__ void gemm_tiled(const float* __restrict__ in,
                           const float* __restrict__ W,
                           float* __restrict__ out, int n) {
    constexpr int QUADS = DOUT / 4;      // 16
    constexpr int NPB   = (128 / QUADS) * 4;  // 32 nodes/block
    constexpr int KQ    = DIN / 4;

    __shared__ __align__(16) float Ws[DIN * DOUT];
    __shared__ __align__(16) float xs[DIN][NPB];

    const int tid = threadIdx.x;
    const int node0 = blockIdx.x * NPB;

    #pragma unroll 4
    for (int i = tid; i < DIN * DOUT / 4; i += 128)
        reinterpret_cast<float4*>(Ws)[i] = reinterpret_cast<const float4*>(W)[i];

    for (int i = tid; i < NPB * KQ; i += 128) {
        int nn = i / KQ;
        int kk = i % KQ;
        int node = node0 + nn;
        float4 v = make_float4(0.f, 0.f, 0.f, 0.f);
        if (node < n)
            v = reinterpret_cast<const float4*>(in + (size_t)node * DIN)[kk];
        xs[kk * 4 + 0][nn] = v.x;
        xs[kk * 4 + 1][nn] = v.y;
        xs[kk * 4 + 2][nn] = v.z;
        xs[kk * 4 + 3][nn] = v.w;
    }
    __syncthreads();

    const int quad  = tid % QUADS;
    const int nbase = (tid / QUADS) * 4;

    float4 a0 = {}, a1 = {}, a2 = {}, a3 = {};
    #pragma unroll 4
    for (int k = 0; k < DIN; k++) {
        float4 xv = *reinterpret_cast<const float4*>(&xs[k][nbase]);
        float4 w  = reinterpret_cast<const float4*>(Ws)[k * QUADS + quad];
        a0.x = fmaf(xv.x, w.x, a0.x); a0.y = fmaf(xv.x, w.y, a0.y);
        a0.z = fmaf(xv.x, w.z, a0.z); a0.w = fmaf(xv.x, w.w, a0.w);
        a1.x = fmaf(xv.y, w.x, a1.x); a1.y = fmaf(xv.y, w.y, a1.y);
        a1.z = fmaf(xv.y, w.z, a1.z); a1.w = fmaf(xv.y, w.w, a1.w);
        a2.x = fmaf(xv.z, w.x, a2.x); a2.y = fmaf(xv.z, w.y, a2.y);
        a2.z = fmaf(xv.z, w.z, a2.z); a2.w = fmaf(xv.z, w.w, a2.w);
        a3.x = fmaf(xv.w, w.x, a3.x); a3.y = fmaf(xv.w, w.y, a3.y);
        a3.z = fmaf(xv.w, w.z, a3.z); a3.w = fmaf(xv.w, w.w, a3.w);
    }
    float4 accs[4] = {a0, a1, a2, a3};
    #pragma unroll
    for (int i = 0; i < 4; i++) {
        int node = node0 + nbase + i;
        if (node < n)
            reinterpret_cast<float4*>(out + (size_t)node * DOUT)[quad] = accs[i];
    }
}

// ---------------------------------------------------------------------------
// Small GEMM with fused tanh on input: out[n,16] = tanh(in[n,64]) @ W[64,16]
// ---------------------------------------------------------------------------
__global__ void gemm_tanh16(const float* __restrict__ in,
                            const float* __restrict__ W,
                            float* __restrict__ out, int n) {
    constexpr int DIN = DIM_H, DOUT = DIM_OUT;
    constexpr int TPN = DOUT / 4;      // 4
    constexpr int NPB = 128 / TPN;     // 32
    __shared__ __align__(16) float Ws[DIN * DOUT];
    __shared__ __align__(16) float xs[NPB][DIN + 4];

    const int tid = threadIdx.x;
    const int node0 = blockIdx.x * NPB;

    for (int i = tid; i < DIN * DOUT / 4; i += 128)
        reinterpret_cast<float4*>(Ws)[i] = reinterpret_cast<const float4*>(W)[i];

    for (int i = tid; i < NPB * (DIN / 4); i += 128) {
        int nn = i / (DIN / 4);
        int kk = i % (DIN / 4);
        float4 v = make_float4(0.f, 0.f, 0.f, 0.f);
        int node = node0 + nn;
        if (node < n)
            v = reinterpret_cast<const float4*>(in + (size_t)node * DIN)[kk];
        v.x = tanhf(v.x); v.y = tanhf(v.y); v.z = tanhf(v.z); v.w = tanhf(v.w);
        reinterpret_cast<float4*>(&xs[nn][0])[kk] = v;
    }
    __syncthreads();

    const int local = tid / TPN;
    const int jq    = tid % TPN;
    const int node  = node0 + local;

    float4 acc = make_float4(0.f, 0.f, 0.f, 0.f);
    #pragma unroll 8
    for (int k = 0; k < DIN; k++) {
        float  xv = xs[local][k];
        float4 w  = reinterpret_cast<float4*>(Ws)[k * TPN + jq];
        acc.x = fmaf(xv, w.x, acc.x);
        acc.y = fmaf(xv, w.y, acc.y);
        acc.z = fmaf(xv, w.z, acc.z);
        acc.w = fmaf(xv, w.w, acc.w);
    }
    if (node < n)
        reinterpret_cast<float4*>(out + (size_t)node * DOUT)[jq] = acc;
}

// ---------------------------------------------------------------------------
// CSR SpMM d=64: one warp per node. No atomics; accumulate in registers.
// Lane handles cols lane and lane+32. Edge loop unrolled x2 for MLP.
// ---------------------------------------------------------------------------
__global__ void spmm64_csr(const int* __restrict__ rowptr,
                           const int2* __restrict__ spack,
                           const float* __restrict__ h,
                           float* __restrict__ out, int n) {
    int warp = (blockIdx.x * blockDim.x + threadIdx.x) >> 5;
    if (warp >= n) return;
    int lane = threadIdx.x & 31;
    int beg = __ldg(&rowptr[warp]);
    int end = __ldg(&rowptr[warp + 1]);
    float acc0 = 0.f, acc1 = 0.f;
    int j = beg;
    for (; j + 1 < end; j += 2) {
        int2 p0 = __ldg(&spack[j]);
        int2 p1 = __ldg(&spack[j + 1]);
        const float* h0 = h + (size_t)p0.x * 64;
        const float* h1 = h + (size_t)p1.x * 64;
        float v0 = __int_as_float(p0.y);
        float v1 = __int_as_float(p1.y);
        float a0 = __ldg(h0 + lane);
        float b0 = __ldg(h0 + lane + 32);
        float a1 = __ldg(h1 + lane);
        float b1 = __ldg(h1 + lane + 32);
        acc0 = fmaf(v0, a0, acc0);
        acc1 = fmaf(v0, b0, acc1);
        acc0 = fmaf(v1, a1, acc0);
        acc1 = fmaf(v1, b1, acc1);
    }
    if (j < end) {
        int2 p = __ldg(&spack[j]);
        const float* hr = h + (size_t)p.x * 64;
        float v = __int_as_float(p.y);
        acc0 = fmaf(v, __ldg(hr + lane), acc0);
        acc1 = fmaf(v, __ldg(hr + lane + 32), acc1);
    }
    out[(size_t)warp * 64 + lane] = acc0;
    out[(size_t)warp * 64 + lane + 32] = acc1;
}

// ---------------------------------------------------------------------------
// CSR SpMM d=16: 16 threads per node (2 nodes per warp). No atomics.
// ---------------------------------------------------------------------------
__global__ void spmm16_csr(const int* __restrict__ rowptr,
                           const int2* __restrict__ spack,
                           const float* __restrict__ h,
                           float* __restrict__ out, int n) {
    int g = blockIdx.x * blockDim.x + threadIdx.x;
    int node = g >> 4;
    if (node >= n) return;
    int f = g & 15;
    int beg = __ldg(&rowptr[node]);
    int end = __ldg(&rowptr[node + 1]);
    float acc = 0.f;
    int j = beg;
    for (; j + 1 < end; j += 2) {
        int2 p0 = __ldg(&spack[j]);
        int2 p1 = __ldg(&spack[j + 1]);
        float a0 = __ldg(h + (size_t)p0.x * 16 + f);
        float a1 = __ldg(h + (size_t)p1.x * 16 + f);
        acc = fmaf(__int_as_float(p0.y), a0, acc);
        acc = fmaf(__int_as_float(p1.y), a1, acc);
    }
    if (j < end) {
        int2 p = __ldg(&spack[j]);
        acc = fmaf(__int_as_float(p.y), __ldg(h + (size_t)p.x * 16 + f), acc);
    }
    out[(size_t)node * 16 + f] = acc;
}

// ---------------------------------------------------------------------------
// Softmax over 16 columns, one thread per node.
// ---------------------------------------------------------------------------
__global__ void softmax16_kernel(const float* __restrict__ in,
                                 float* __restrict__ out, int n) {
    int i = blockIdx.x * blockDim.x + threadIdx.x;
    if (i >= n) return;
    const float4* r = reinterpret_cast<const float4*>(in + (size_t)i * 16);
    float4 a = r[0], b = r[1], c = r[2], d = r[3];
    float v[16] = {a.x,a.y,a.z,a.w, b.x,b.y,b.z,b.w,
                   c.x,c.y,c.z,c.w, d.x,d.y,d.z,d.w};
    float m = v[0];
    #pragma unroll
    for (int k = 1; k < 16; k++) m = fmaxf(m, v[k]);
    float sum = 0.f;
    #pragma unroll
    for (int k = 0; k < 16; k++) { v[k] = __expf(v[k] - m); sum += v[k]; }
    float inv = 1.f / sum;
    float4* w = reinterpret_cast<float4*>(out + (size_t)i * 16);
    w[0] = make_float4(v[0]*inv,  v[1]*inv,  v[2]*inv,  v[3]*inv);
    w[1] = make_float4(v[4]*inv,  v[5]*inv,  v[6]*inv,  v[7]*inv);
    w[2] = make_float4(v[8]*inv,  v[9]*inv,  v[10]*inv, v[11]*inv);
    w[3] = make_float4(v[12]*inv, v[13]*inv, v[14]*inv, v[15]*inv);
}

// ---------------------------------------------------------------------------
// Launch
// ---------------------------------------------------------------------------
extern "C" void kernel_launch(void* const* d_in, const int* in_sizes, int n_in,
                              void* d_out, int out_size) {
    const float* x        = (const float*)d_in[0];
    const int*   edge_src = (const int*)d_in[1];
    const int*   edge_dst = (const int*)d_in[2];
    const float* edge_val = (const float*)d_in[3];
    const float* W1       = (const float*)d_in[4];
    const float* W2       = (const float*)d_in[5];
    const float* W3       = (const float*)d_in[6];
    float* out = (float*)d_out;

    const int N = in_sizes[0] / DIM_IN;   // 50000
    const int E = in_sizes[1];            // 800000

    float *A, *B, *C, *U, *D, *W23;
    int *cnt, *cur, *rowptr, *bsum;
    int2 *spack;
    cudaGetSymbolAddress((void**)&A, g_A);
    cudaGetSymbolAddress((void**)&B, g_B);
    cudaGetSymbolAddress((void**)&C, g_C);
    cudaGetSymbolAddress((void**)&U, g_U);
    cudaGetSymbolAddress((void**)&D, g_D);
    cudaGetSymbolAddress((void**)&W23, g_W23);
    cudaGetSymbolAddress((void**)&cnt, g_cnt);
    cudaGetSymbolAddress((void**)&cur, g_cur);
    cudaGetSymbolAddress((void**)&rowptr, g_rowptr);
    cudaGetSymbolAddress((void**)&bsum, g_bsum);
    cudaGetSymbolAddress((void**)&spack, g_spack);

    const int NB = (N + 511) / 512;       // 98 scan blocks

    // --- CSR build (reused by all 3 SpMMs) ---
    zero_cnt_kernel<<<(N + 255) / 256, 256>>>(cnt, N);
    hist_kernel<<<(E + 255) / 256, 256>>>(edge_dst, cnt, E);
    scan1_kernel<<<NB, 512>>>(cnt, rowptr, bsum, N);
    scan2_kernel<<<1, 128>>>(bsum, NB);
    scan3_kernel<<<(N + 255) / 256, 256>>>(rowptr, bsum, cur, N, E);
    scatter_kernel<<<(E + 255) / 256, 256>>>(edge_src, edge_dst, edge_val, cur, spack, E);

    // --- W23 = W2 @ W3 ---
    w23_kernel<<<4, 256>>>(W2, W3, W23);

    // A = x @ W1
    gemm_tiled<DIM_IN, DIM_H><<<(N + 31) / 32, 128>>>(x, W1, A, N);

    // B = spmm(A)   [d=64, CSR, no atomics]
    spmm64_csr<<<(N * 32 + 255) / 256, 256>>>(rowptr, spack, A, B, N);

    // C = tanh(B) @ W23   [50k,16]
    gemm_tanh16<<<(N + 31) / 32, 128>>>(B, W23, C, N);

    // U = spmm(C)   [d=16, CSR]
    spmm16_csr<<<(N * 16 + 255) / 256, 256>>>(rowptr, spack, C, U, N);

    // D = spmm(U)   [d=16, CSR]
    spmm16_csr<<<(N * 16 + 255) / 256, 256>>>(rowptr, spack, U, D, N);

    // out = softmax(D)
    softmax16_kernel<<<(N + 255) / 256, 256>>>(D, out, N);
}

// round 16
// speedup vs baseline: 1.0467x; 1.0467x over previous
#include <cuda_runtime.h>
#include <cuda_bf16.h>
#include <math.h>

#define N_NODES 50000
#define N_EDGES 800000
#define DIM_IN  128
#define DIM_H   64
#define DIM_OUT 16

// Scratch (allocation-free: __device__ globals)
__device__ __align__(16) float g_A[N_NODES * DIM_H];    // gemm1 out
__device__ __align__(16) float g_B[N_NODES * DIM_H];    // spmm64 out
__device__ __align__(16) float g_C[N_NODES * DIM_OUT];  // tanh(B)@W23
__device__ __align__(16) float g_U[N_NODES * DIM_OUT];  // spmm16 #1 out
__device__ __align__(16) float g_W23[DIM_H * DIM_OUT];  // W2@W3

// CSR build scratch
__device__ int  g_cnt[N_NODES];
__device__ int  g_cur[N_NODES];
__device__ int  g_rowptr[N_NODES + 1];
__device__ int  g_bsum[256];
__device__ __align__(8) int2 g_spack[N_EDGES];  // dst-sorted (src, val_bits)

// ---------------------------------------------------------------------------
// Merged: zero histogram + W23 = W2@W3 (independent prologue work)
// ---------------------------------------------------------------------------
__global__ void zw_kernel(int* __restrict__ cnt, int n,
                          const float* __restrict__ W2,
                          const float* __restrict__ W3,
                          float* __restrict__ W23) {
    int i = blockIdx.x * blockDim.x + threadIdx.x;
    if (i < n) cnt[i] = 0;
    if (i < DIM_H * DIM_OUT) {
        int r = i / DIM_OUT, c = i % DIM_OUT;
        float s = 0.f;
        #pragma unroll 8
        for (int k = 0; k < DIM_H; k++)
            s = fmaf(W2[r * DIM_H + k], W3[k * DIM_OUT + c], s);
        W23[i] = s;
    }
}

// ---------------------------------------------------------------------------
// CSR build: histogram of dst
// ---------------------------------------------------------------------------
__global__ void hist_kernel(const int* __restrict__ dst, int* __restrict__ cnt, int E) {
    int e = blockIdx.x * blockDim.x + threadIdx.x;
    if (e < E) atomicAdd(&cnt[dst[e]], 1);
}

// ---------------------------------------------------------------------------
// CSR build: per-block exclusive scan (512/block), block totals out
// ---------------------------------------------------------------------------
__global__ void scan1_kernel(const int* __restrict__ cnt, int* __restrict__ rowptr,
                             int* __restrict__ bsum, int n) {
    __shared__ int sh[512];
    int tid = threadIdx.x;
    int i = blockIdx.x * 512 + tid;
    int v = (i < n) ? cnt[i] : 0;
    sh[tid] = v;
    __syncthreads();
    #pragma unroll
    for (int off = 1; off < 512; off <<= 1) {
        int t = (tid >= off) ? sh[tid - off] : 0;
        __syncthreads();
        sh[tid] += t;
        __syncthreads();
    }
    if (i < n) rowptr[i] = sh[tid] - v;   // exclusive within block
    if (tid == 511) bsum[blockIdx.x] = sh[511];
}

// ---------------------------------------------------------------------------
// CSR build: merged scan2+scan3. Each 256-thread block covers 256 indices that
// all share the same 512-scan-block (i>>9 is constant per block), so it
// redundantly block-reduces bsum[0 .. blk>>1) for its single offset.
// ---------------------------------------------------------------------------
__global__ void scan23_kernel(int* __restrict__ rowptr, const int* __restrict__ bsum,
                              int* __restrict__ cur, int n, int E) {
    __shared__ int sh[256];
    int tid = threadIdx.x;
    int bneed = blockIdx.x >> 1;          // # of preceding 512-blocks
    sh[tid] = (tid < bneed) ? bsum[tid] : 0;
    __syncthreads();
    #pragma unroll
    for (int off = 128; off > 0; off >>= 1) {
        if (tid < off) sh[tid] += sh[tid + off];
        __syncthreads();
    }
    int offset = sh[0];
    int i = blockIdx.x * 256 + tid;
    if (i < n) {
        int v = rowptr[i] + offset;
        rowptr[i] = v;
        cur[i] = v;
    }
    if (blockIdx.x == 0 && tid == 0) rowptr[n] = E;
}

// ---------------------------------------------------------------------------
// CSR build: scatter edges into dst-sorted pack
// ---------------------------------------------------------------------------
__global__ void scatter_kernel(const int* __restrict__ src, const int* __restrict__ dst,
                               const float* __restrict__ val, int* __restrict__ cur,
                               int2* __restrict__ spack, int E) {
    int e = blockIdx.x * blockDim.x + threadIdx.x;
    if (e >= E) return;
    int d = dst[e];
    int p = atomicAdd(&cur[d], 1);
    spack[p] = make_int2(src[e], __float_as_int(val[e]));
}

// ---------------------------------------------------------------------------
// GEMM1: out[n,64] = in[n,128] @ W[128,64].
// 128 threads; 64 nodes/block; thread = 4 nodes x 8 cols (32 acc regs).
// x staged transposed in 2 k-tiles of 64. 48KB static smem.
// ---------------------------------------------------------------------------
template <int DIN, int DOUT>
__global__ void gemm_tiled48(const float* __restrict__ in,
                             const float* __restrict__ W,
                             float* __restrict__ out, int n) {
    constexpr int OCTS  = DOUT / 8;       // 8
    constexpr int NPB   = (128 / OCTS) * 4;  // 64 nodes/block
    constexpr int KT    = 64;             // k-tile
    constexpr int NKT   = DIN / KT;       // 2
    constexpr int WQ    = DOUT / 4;       // float4s per W row

    __shared__ __align__(16) float Ws[DIN * DOUT];   // 32KB
    __shared__ __align__(16) float xs[KT][NPB];      // 16KB

    const int tid = threadIdx.x;
    const int node0 = blockIdx.x * NPB;

    #pragma unroll 4
    for (int i = tid; i < DIN * DOUT / 4; i += 128)
        reinterpret_cast<float4*>(Ws)[i] = reinterpret_cast<const float4*>(W)[i];

    const int oct   = tid % OCTS;
    const int nbase = (tid / OCTS) * 4;

    float4 acc[4][2] = {};

    for (int kt = 0; kt < NKT; kt++) {
        __syncthreads();   // xs reuse barrier (and W-ready on first iter)
        for (int i = tid; i < NPB * (KT / 4); i += 128) {
            int nn = i / (KT / 4);
            int kk = i % (KT / 4);
            int node = node0 + nn;
            float4 v = make_float4(0.f, 0.f, 0.f, 0.f);
            if (node < n)
                v = reinterpret_cast<const float4*>(in + (size_t)node * DIN)[kt * (KT / 4) + kk];
            xs[kk * 4 + 0][nn] = v.x;
            xs[kk * 4 + 1][nn] = v.y;
            xs[kk * 4 + 2][nn] = v.z;
            xs[kk * 4 + 3][nn] = v.w;
        }
        __syncthreads();

        #pragma unroll 4
        for (int k = 0; k < KT; k++) {
            float4 xv = *reinterpret_cast<const float4*>(&xs[k][nbase]);
            const float4* wr = reinterpret_cast<const float4*>(Ws) + (kt * KT + k) * WQ;
            float4 w0 = wr[oct * 2];
            float4 w1 = wr[oct * 2 + 1];
            float xn[4] = {xv.x, xv.y, xv.z, xv.w};
            #pragma unroll
            for (int i = 0; i < 4; i++) {
                acc[i][0].x = fmaf(xn[i], w0.x, acc[i][0].x);
                acc[i][0].y = fmaf(xn[i], w0.y, acc[i][0].y);
                acc[i][0].z = fmaf(xn[i], w0.z, acc[i][0].z);
                acc[i][0].w = fmaf(xn[i], w0.w, acc[i][0].w);
                acc[i][1].x = fmaf(xn[i], w1.x, acc[i][1].x);
                acc[i][1].y = fmaf(xn[i], w1.y, acc[i][1].y);
                acc[i][1].z = fmaf(xn[i], w1.z, acc[i][1].z);
                acc[i][1].w = fmaf(xn[i], w1.w, acc[i][1].w);
            }
        }
    }

    #pragma unroll
    for (int i = 0; i < 4; i++) {
        int node = node0 + nbase + i;
        if (node < n) {
            float4* o = reinterpret_cast<float4*>(out + (size_t)node * DOUT);
            o[oct * 2]     = acc[i][0];
            o[oct * 2 + 1] = acc[i][1];
        }
    }
}

// ---------------------------------------------------------------------------
// Small GEMM with fused tanh on input: out[n,16] = tanh(in[n,64]) @ W[64,16]
// ---------------------------------------------------------------------------
__global__ void gemm_tanh16(const float* __restrict__ in,
                            const float* __restrict__ W,
                            float* __restrict__ out, int n) {
    constexpr int DIN = DIM_H, DOUT = DIM_OUT;
    constexpr int TPN = DOUT / 4;      // 4
    constexpr int NPB = 128 / TPN;     // 32
    __shared__ __align__(16) float Ws[DIN * DOUT];
    __shared__ __align__(16) float xs[NPB][DIN + 4];

    const int tid = threadIdx.x;
    const int node0 = blockIdx.x * NPB;

    for (int i = tid; i < DIN * DOUT / 4; i += 128)
        reinterpret_cast<float4*>(Ws)[i] = reinterpret_cast<const float4*>(W)[i];

    for (int i = tid; i < NPB * (DIN / 4); i += 128) {
        int nn = i / (DIN / 4);
        int kk = i % (DIN / 4);
        float4 v = make_float4(0.f, 0.f, 0.f, 0.f);
        int node = node0 + nn;
        if (node < n)
            v = reinterpret_cast<const float4*>(in + (size_t)node * DIN)[kk];
        v.x = tanhf(v.x); v.y = tanhf(v.y); v.z = tanhf(v.z); v.w = tanhf(v.w);
        reinterpret_cast<float4*>(&xs[nn][0])[kk] = v;
    }
    __syncthreads();

    const int local = tid / TPN;
    const int jq    = tid % TPN;
    const int node  = node0 + local;

    float4 acc = make_float4(0.f, 0.f, 0.f, 0.f);
    #pragma unroll 8
    for (int k = 0; k < DIN; k++) {
        float  xv = xs[local][k];
        float4 w  = reinterpret_cast<float4*>(Ws)[k * TPN + jq];
        acc.x = fmaf(xv, w.x, acc.x);
        acc.y = fmaf(xv, w.y, acc.y);
        acc.z = fmaf(xv, w.z, acc.z);
        acc.w = fmaf(xv, w.w, acc.w);
    }
    if (node < n)
        reinterpret_cast<float4*>(out + (size_t)node * DOUT)[jq] = acc;
}

// ---------------------------------------------------------------------------
// CSR SpMM d=64: one warp per node. No atomics; accumulate in registers.
// ---------------------------------------------------------------------------
__global__ void spmm64_csr(const int* __restrict__ rowptr,
                           const int2* __restrict__ spack,
                           const float* __restrict__ h,
                           float* __restrict__ out, int n) {
    int warp = (blockIdx.x * blockDim.x + threadIdx.x) >> 5;
    if (warp >= n) return;
    int lane = threadIdx.x & 31;
    int beg = __ldg(&rowptr[warp]);
    int end = __ldg(&rowptr[warp + 1]);
    float acc0 = 0.f, acc1 = 0.f;
    int j = beg;
    for (; j + 1 < end; j += 2) {
        int2 p0 = __ldg(&spack[j]);
        int2 p1 = __ldg(&spack[j + 1]);
        const float* h0 = h + (size_t)p0.x * 64;
        const float* h1 = h + (size_t)p1.x * 64;
        float v0 = __int_as_float(p0.y);
        float v1 = __int_as_float(p1.y);
        float a0 = __ldg(h0 + lane);
        float b0 = __ldg(h0 + lane + 32);
        float a1 = __ldg(h1 + lane);
        float b1 = __ldg(h1 + lane + 32);
        acc0 = fmaf(v0, a0, acc0);
        acc1 = fmaf(v0, b0, acc1);
        acc0 = fmaf(v1, a1, acc0);
        acc1 = fmaf(v1, b1, acc1);
    }
    if (j < end) {
        int2 p = __ldg(&spack[j]);
        const float* hr = h + (size_t)p.x * 64;
        float v = __int_as_float(p.y);
        acc0 = fmaf(v, __ldg(hr + lane), acc0);
        acc1 = fmaf(v, __ldg(hr + lane + 32), acc1);
    }
    out[(size_t)warp * 64 + lane] = acc0;
    out[(size_t)warp * 64 + lane + 32] = acc1;
}

// ---------------------------------------------------------------------------
// CSR SpMM d=16: 16 threads per node. No atomics.
// ---------------------------------------------------------------------------
__global__ void spmm16_csr(const int* __restrict__ rowptr,
                           const int2* __restrict__ spack,
                           const float* __restrict__ h,
                           float* __restrict__ out, int n) {
    int g = blockIdx.x * blockDim.x + threadIdx.x;
    int node = g >> 4;
    if (node >= n) return;
    int f = g & 15;
    int beg = __ldg(&rowptr[node]);
    int end = __ldg(&rowptr[node + 1]);
    float acc = 0.f;
    int j = beg;
    for (; j + 1 < end; j += 2) {
        int2 p0 = __ldg(&spack[j]);
        int2 p1 = __ldg(&spack[j + 1]);
        float a0 = __ldg(h + (size_t)p0.x * 16 + f);
        float a1 = __ldg(h + (size_t)p1.x * 16 + f);
        acc = fmaf(__int_as_float(p0.y), a0, acc);
        acc = fmaf(__int_as_float(p1.y), a1, acc);
    }
    if (j < end) {
        int2 p = __ldg(&spack[j]);
        acc = fmaf(__int_as_float(p.y), __ldg(h + (size_t)p.x * 16 + f), acc);
    }
    out[(size_t)node * 16 + f] = acc;
}

// ---------------------------------------------------------------------------
// CSR SpMM d=16 + fused softmax over the 16 lanes of each node group.
// All threads stay active for shfl safety (invalid nodes compute on zeros).
// ---------------------------------------------------------------------------
__global__ void spmm16_softmax(const int* __restrict__ rowptr,
                               const int2* __restrict__ spack,
                               const float* __restrict__ h,
                               float* __restrict__ out, int n) {
    int g = blockIdx.x * blockDim.x + threadIdx.x;
    int node = g >> 4;
    int f = g & 15;
    bool valid = node < n;
    int beg = 0, end = 0;
    if (valid) {
        beg = __ldg(&rowptr[node]);
        end = __ldg(&rowptr[node + 1]);
    }
    float acc = 0.f;
    int j = beg;
    for (; j + 1 < end; j += 2) {
        int2 p0 = __ldg(&spack[j]);
        int2 p1 = __ldg(&spack[j + 1]);
        float a0 = __ldg(h + (size_t)p0.x * 16 + f);
        float a1 = __ldg(h + (size_t)p1.x * 16 + f);
        acc = fmaf(__int_as_float(p0.y), a0, acc);
        acc = fmaf(__int_as_float(p1.y), a1, acc);
    }
    if (j < end) {
        int2 p = __ldg(&spack[j]);
        acc = fmaf(__int_as_float(p.y), __ldg(h + (size_t)p.x * 16 + f), acc);
    }
    // softmax across the 16-lane group (xor masks < 16 stay within the group)
    float m = acc;
    #pragma unroll
    for (int mask = 8; mask > 0; mask >>= 1)
        m = fmaxf(m, __shfl_xor_sync(0xFFFFFFFFu, m, mask));
    float e = __expf(acc - m);
    float s = e;
    #pragma unroll
    for (int mask = 8; mask > 0; mask >>= 1)
        s += __shfl_xor_sync(0xFFFFFFFFu, s, mask);
    if (valid)
        out[(size_t)node * 16 + f] = e / s;
}

// ---------------------------------------------------------------------------
// Launch
// ---------------------------------------------------------------------------
extern "C" void kernel_launch(void* const* d_in, const int* in_sizes, int n_in,
                              void* d_out, int out_size) {
    const float* x        = (const float*)d_in[0];
    const int*   edge_src = (const int*)d_in[1];
    const int*   edge_dst = (const int*)d_in[2];
    const float* edge_val = (const float*)d_in[3];
    const float* W1       = (const float*)d_in[4];
    const float* W2       = (const float*)d_in[5];
    const float* W3       = (const float*)d_in[6];
    float* out = (float*)d_out;

    const int N = in_sizes[0] / DIM_IN;   // 50000
    const int E = in_sizes[1];            // 800000

    float *A, *B, *C, *U, *W23;
    int *cnt, *cur, *rowptr, *bsum;
    int2 *spack;
    cudaGetSymbolAddress((void**)&A, g_A);
    cudaGetSymbolAddress((void**)&B, g_B);
    cudaGetSymbolAddress((void**)&C, g_C);
    cudaGetSymbolAddress((void**)&U, g_U);
    cudaGetSymbolAddress((void**)&W23, g_W23);
    cudaGetSymbolAddress((void**)&cnt, g_cnt);
    cudaGetSymbolAddress((void**)&cur, g_cur);
    cudaGetSymbolAddress((void**)&rowptr, g_rowptr);
    cudaGetSymbolAddress((void**)&bsum, g_bsum);
    cudaGetSymbolAddress((void**)&spack, g_spack);

    // 1. zero hist + W23 (merged)
    zw_kernel<<<(N + 255) / 256, 256>>>(cnt, N, W2, W3, W23);
    // 2. histogram of dst
    hist_kernel<<<(E + 255) / 256, 256>>>(edge_dst, cnt, E);
    // 3. per-block scan
    scan1_kernel<<<(N + 511) / 512, 512>>>(cnt, rowptr, bsum, N);
    // 4. merged block-offset apply + cursor init
    scan23_kernel<<<(N + 255) / 256, 256>>>(rowptr, bsum, cur, N, E);
    // 5. scatter into dst-sorted pack
    scatter_kernel<<<(E + 255) / 256, 256>>>(edge_src, edge_dst, edge_val, cur, spack, E);

    // 6. A = x @ W1
    gemm_tiled48<DIM_IN, DIM_H><<<(N + 63) / 64, 128>>>(x, W1, A, N);
    // 7. B = spmm(A)   [d=64, CSR]
    spmm64_csr<<<(N * 32 + 255) / 256, 256>>>(rowptr, spack, A, B, N);
    // 8. C = tanh(B) @ W23
    gemm_tanh16<<<(N + 31) / 32, 128>>>(B, W23, C, N);
    // 9. U = spmm(C)   [d=16, CSR]
    spmm16_csr<<<(N * 16 + 255) / 256, 256>>>(rowptr, spack, C, U, N);
    // 10. out = softmax(spmm(U))   [d=16, CSR + fused softmax]
    spmm16_softmax<<<(N * 16 + 255) / 256, 256>>>(rowptr, spack, U, out, N);
}